// round 13
// baseline (speedup 1.0000x reference)
#include <cuda_runtime.h>
#include <math.h>

#define EPS 1e-5f

// ---------------- scratch (device globals; no allocation) ----------------
__device__ float g_x[8*1024*64];        // BN'd x, NHWC (residual)
__device__ float g_x1[8*1024*128];      // in_proj x1 (pre-conv), NHWC
__device__ float g_zs[8*1024*128];      // silu(z), NHWC
__device__ float g_x1s[8*1024*128];     // conv+silu output, NHWC
__device__ float g_xdbl[8*4*36*1024];   // (b,k,c,l): rows 0-3 dts, 4-19 B, 20-35 C
__device__ float g_ys[8*4*1024*128];    // (b,k,l,d)
__device__ float g_q[32*128*16];        // carry h at l=512 per (bk,d,n)
__device__ float g_zj[8*576];           // [z_rgb(256), z_dem(256), z_mamba(64)]
__device__ float g_wgt[8*512];

// scan-order index l (direction k) -> spatial position p
__device__ __forceinline__ int perm_idx(int k, int l) {
    int m = (k >= 2) ? (1023 - l) : l;
    if (k & 1) m = (m & 31) * 32 + (m >> 5);
    return m;
}

// ---------------- K0: channel means of rgb/dem + zero z_mamba ----------------
__global__ __launch_bounds__(256) void k0_means(const float* __restrict__ rgb,
                                                const float* __restrict__ dem) {
    int t = threadIdx.x, blk = blockIdx.x;
    if (blk == 0) {
        #pragma unroll
        for (int q = 0; q < 2; q++) {
            int i = q * 256 + t;               // 0..511: all 8 batches x 64
            g_zj[(i >> 6) * 576 + 512 + (i & 63)] = 0.f;
        }
    }
    int gw = blk * 8 + (t >> 5);
    int lane = t & 31;
    const float* src = (gw < 2048) ? rgb : dem;
    int cc = gw & 2047;
    const float* ptr = src + cc * 1024;
    float s = 0.f;
    #pragma unroll
    for (int i = 0; i < 32; i++) s += ptr[lane + i * 32];
    #pragma unroll
    for (int o = 16; o; o >>= 1) s += __shfl_xor_sync(0xffffffffu, s, o);
    if (lane == 0) {
        int b = cc >> 8, c = cc & 255;
        g_zj[b * 576 + ((gw < 2048) ? c : 256 + c)] = s * (1.f / 1024.f);
    }
}

// ---------------- K1: (rgb+dem) -> reduce GEMM -> BN -> LN -> in_proj ----------------
// 512 blocks (b, h, half-row of 16 pixels) x 256 threads.
__global__ __launch_bounds__(256) void k1_front(
    const float* __restrict__ rgb, const float* __restrict__ dem,
    const float* __restrict__ wred,
    const float* __restrict__ bg, const float* __restrict__ bb,
    const float* __restrict__ bm, const float* __restrict__ bv,
    const float* __restrict__ lg, const float* __restrict__ lb,
    const float* __restrict__ ipw)
{
    __shared__ float s_buf[8448];    // phase A: s_in[256][17] (first 4352); phase D: s_jw[64][132]
    __shared__ float s_a[2080];      // s_w[32][64]
    __shared__ float s_xn[16 * 65];
    __shared__ float s_r1[256], s_r2[256];
    __shared__ float s_mu[16], s_rs[16];

    int t = threadIdx.x;
    int blk = blockIdx.x;
    int b = blk >> 6, rh = blk & 63;
    int h = rh >> 1, hf = rh & 1;
    int w0 = hf * 16;

    // phase A: load input tile (rgb+dem) 256c x 16w
    const float* rp = rgb + b * 262144 + h * 32 + w0;
    const float* dp = dem + b * 262144 + h * 32 + w0;
    #pragma unroll 4
    for (int i = 0; i < 16; i++) {
        int idx = i * 256 + t; int c = idx >> 4, w = idx & 15;
        s_buf[c * 17 + w] = rp[c * 1024 + w] + dp[c * 1024 + w];
    }
    __syncthreads();

    int w = t & 15, og = t >> 4;     // og in [0,16): 4 outputs each
    float acc[4];
    #pragma unroll
    for (int j = 0; j < 4; j++) acc[j] = 0.f;

    // phase B: reduce GEMM (weights staged per 32-c chunk)
    for (int cb = 0; cb < 256; cb += 32) {
        __syncthreads();
        #pragma unroll
        for (int i = 0; i < 8; i++) {
            int idx = i * 256 + t; int c2 = idx & 31, o2 = idx >> 5;
            s_a[c2 * 64 + o2] = wred[o2 * 256 + cb + c2];
        }
        __syncthreads();
        #pragma unroll 8
        for (int c2 = 0; c2 < 32; c2++) {
            float v = s_buf[(cb + c2) * 17 + w];
            float4 w4 = *reinterpret_cast<const float4*>(&s_a[c2 * 64 + og * 4]);
            acc[0] += v * w4.x; acc[1] += v * w4.y; acc[2] += v * w4.z; acc[3] += v * w4.w;
        }
    }

    // phase C: BN, store g_x, LN
    int p = h * 32 + w0 + w;
    float xr[4]; float s1 = 0.f, s2 = 0.f;
    #pragma unroll
    for (int j = 0; j < 4; j++) {
        int o = og * 4 + j;
        float v = (acc[j] - bm[o]) * rsqrtf(bv[o] + EPS) * bg[o] + bb[o];
        xr[j] = v; s1 += v; s2 += v * v;
    }
    *reinterpret_cast<float4*>(g_x + (b * 1024 + p) * 64 + og * 4) =
        make_float4(xr[0], xr[1], xr[2], xr[3]);
    s_r1[t] = s1; s_r2[t] = s2;
    __syncthreads();
    if (t < 16) {
        float a = 0.f, q = 0.f;
        #pragma unroll
        for (int g = 0; g < 16; g++) { a += s_r1[g * 16 + t]; q += s_r2[g * 16 + t]; }
        float mu = a * (1.f / 64.f);
        float var = q * (1.f / 64.f) - mu * mu;
        s_mu[t] = mu; s_rs[t] = rsqrtf(var + EPS);
    }
    __syncthreads();
    {
        float mu = s_mu[w], rs = s_rs[w];
        #pragma unroll
        for (int j = 0; j < 4; j++) {
            int o = og * 4 + j;
            s_xn[w * 65 + o] = (xr[j] - mu) * rs * lg[o] + lb[o];
        }
    }
    __syncthreads();

    // phase D: in_proj, two passes (x1 rows 0..127, z rows 128..255)
    int jg = t >> 4;                 // 8 outputs each: j = jg*8..+8
    for (int pj = 0; pj < 2; pj++) {
        __syncthreads();
        #pragma unroll 4
        for (int i = 0; i < 32; i++) {
            int idx = i * 256 + t; int o = idx & 63, j = idx >> 6;
            s_buf[o * 132 + j] = ipw[(pj * 128 + j) * 64 + o];
        }
        __syncthreads();
        float a2[8];
        #pragma unroll
        for (int j = 0; j < 8; j++) a2[j] = 0.f;
        #pragma unroll 4
        for (int o = 0; o < 64; o++) {
            float xv = s_xn[w * 65 + o];
            const float* wr0 = &s_buf[o * 132 + jg * 8];
            float4 q0 = *reinterpret_cast<const float4*>(wr0);
            float4 q1 = *reinterpret_cast<const float4*>(wr0 + 4);
            a2[0] += xv * q0.x; a2[1] += xv * q0.y; a2[2] += xv * q0.z; a2[3] += xv * q0.w;
            a2[4] += xv * q1.x; a2[5] += xv * q1.y; a2[6] += xv * q1.z; a2[7] += xv * q1.w;
        }
        if (pj == 1) {
            #pragma unroll
            for (int j = 0; j < 8; j++) a2[j] = a2[j] / (1.f + __expf(-a2[j]));
        }
        float* dst = (pj == 0 ? g_x1 : g_zs) + (b * 1024 + p) * 128 + jg * 8;
        *reinterpret_cast<float4*>(dst)     = make_float4(a2[0], a2[1], a2[2], a2[3]);
        *reinterpret_cast<float4*>(dst + 4) = make_float4(a2[4], a2[5], a2[6], a2[7]);
    }
}

// ---------------- K2: depthwise 3x3 conv + bias + silu (NHWC) ----------------
__global__ __launch_bounds__(128) void k2_conv(const float* __restrict__ cw,
                                               const float* __restrict__ cb) {
    int b = blockIdx.x >> 10, p = blockIdx.x & 1023;
    int h = p >> 5, w = p & 31, d = threadIdx.x;
    float s = cb[d];
    #pragma unroll
    for (int i = -1; i <= 1; i++) {
        int hh = h + i; if ((unsigned)hh >= 32u) continue;
        #pragma unroll
        for (int j = -1; j <= 1; j++) {
            int ww = w + j; if ((unsigned)ww >= 32u) continue;
            s += g_x1[(b * 1024 + hh * 32 + ww) * 128 + d] *
                 __ldg(&cw[d * 9 + (i + 1) * 3 + (j + 1)]);
        }
    }
    s = s / (1.f + __expf(-s));
    g_x1s[(b * 1024 + p) * 128 + d] = s;
}

// ---------------- K3: x_dbl = xs @ x_proj_w^T (R7 variant: thread = 9c x 2l) ----------------
__global__ __launch_bounds__(128) void k3_xdbl(const float* __restrict__ xpw) {
    __shared__ float s_u[64 * 132];   // 33792 B
    int blk = blockIdx.x; int bk = blk >> 4, lt = blk & 15;
    int b = bk >> 2, k = bk & 3; int l0 = lt * 64;
    int t = threadIdx.x;
    #pragma unroll 4
    for (int l = 0; l < 64; l++)
        s_u[l * 132 + t] = g_x1s[(b * 1024 + perm_idx(k, l0 + l)) * 128 + t];
    __syncthreads();
    int lsub = t & 31, cg = t >> 5;
    float acc0[9], acc1[9];
    #pragma unroll
    for (int j = 0; j < 9; j++) { acc0[j] = 0.f; acc1[j] = 0.f; }
    const float4* urow0 = reinterpret_cast<const float4*>(&s_u[lsub * 132]);
    const float4* urow1 = reinterpret_cast<const float4*>(&s_u[(lsub + 32) * 132]);
    const float4* wbase = reinterpret_cast<const float4*>(xpw + (k * 36 + cg * 9) * 128);
    #pragma unroll 4
    for (int d4 = 0; d4 < 32; d4++) {
        float4 u0 = urow0[d4];
        float4 u1 = urow1[d4];
        #pragma unroll
        for (int j = 0; j < 9; j++) {
            float4 wv = __ldg(&wbase[j * 32 + d4]);
            acc0[j] += u0.x * wv.x + u0.y * wv.y + u0.z * wv.z + u0.w * wv.w;
            acc1[j] += u1.x * wv.x + u1.y * wv.y + u1.z * wv.z + u1.w * wv.w;
        }
    }
    float* dst = g_xdbl + bk * 36 * 1024 + l0;
    #pragma unroll
    for (int j = 0; j < 9; j++) {
        dst[(cg * 9 + j) * 1024 + lsub]      = acc0[j];
        dst[(cg * 9 + j) * 1024 + lsub + 32] = acc1[j];
    }
}

// ================= K4: two-phase chunked selective scan (R7 variant) =================
__device__ __forceinline__ void dd_compute(
    float2* s_dd, const float* s_dts, int b, int k, int gl0,
    int dl, int lq, int d0, float4 w4, float tb)
{
    #pragma unroll
    for (int i = 0; i < 4; i++) {
        int l = lq + i * 16;
        float x = tb + s_dts[l] * w4.x + s_dts[68 + l] * w4.y
                     + s_dts[136 + l] * w4.z + s_dts[204 + l] * w4.w;
        float e = __expf(x);
        float delta = (x > 20.f) ? x : __logf(1.f + e);
        float u = g_x1s[(b * 1024 + perm_idx(k, gl0 + l)) * 128 + d0 + dl];
        s_dd[dl * 66 + l] = make_float2(delta, delta * u);
    }
}

__global__ __launch_bounds__(128) void k4a_carry(
    const float* __restrict__ alogs,
    const float* __restrict__ dtw, const float* __restrict__ dtb)
{
    __shared__ float s_b[16 * 65];
    __shared__ float s_dts[4 * 68];
    __shared__ float2 s_dd[8 * 66];

    int blk = blockIdx.x;
    int bk = blk >> 4, dg = blk & 15;
    int b = bk >> 2, k = bk & 3;
    int d0 = dg * 8;
    int t = threadIdx.x, warp = t >> 5, lane = t & 31;
    int half = lane >> 4, n = lane & 15;
    int ch = warp * 2 + half;
    int d = d0 + ch;

    float An = -expf(alogs[(k * 128 + d) * 16 + n]);
    int dl = t & 7, lq = t >> 3;
    float4 w4 = *reinterpret_cast<const float4*>(&dtw[(k * 128 + d0 + dl) * 4]);
    float tb = dtb[k * 128 + d0 + dl];

    const float* xd = g_xdbl + bk * 36 * 1024;
    float h = 0.f;

    for (int sc = 0; sc < 8; sc++) {
        int gl0 = sc * 64;
        #pragma unroll
        for (int i = 0; i < 8; i++) {
            int idx = i * 128 + t; int c = idx >> 6, l = idx & 63;
            s_b[c * 65 + l] = xd[(4 + c) * 1024 + gl0 + l];
        }
        #pragma unroll
        for (int i = 0; i < 2; i++) {
            int idx = i * 128 + t; int r = idx >> 6, l = idx & 63;
            s_dts[r * 68 + l] = xd[r * 1024 + gl0 + l];
        }
        __syncthreads();
        dd_compute(s_dd, s_dts, b, k, gl0, dl, lq, d0, w4, tb);
        __syncthreads();
        #pragma unroll 4
        for (int l = 0; l < 64; l++) {
            float2 dd = s_dd[ch * 66 + l];
            float e = __expf(dd.x * An);
            float Bn = s_b[n * 65 + l];
            h = h * e + dd.y * Bn;
        }
        __syncthreads();
    }
    g_q[(bk * 128 + d) * 16 + n] = h;
}

__global__ __launch_bounds__(128) void k4b_scan(
    const float* __restrict__ alogs,
    const float* __restrict__ dtw, const float* __restrict__ dtb)
{
    __shared__ float s_bc[32 * 65];
    __shared__ float s_dts[4 * 68];
    __shared__ float2 s_dd[8 * 66];
    __shared__ float s_y[8 * 66];

    int blk = blockIdx.x;
    int bk = blk >> 5;
    int dg = (blk >> 1) & 15;
    int c1 = blk & 1;
    int b = bk >> 2, k = bk & 3;
    int d0 = dg * 8;
    int t = threadIdx.x, warp = t >> 5, lane = t & 31;
    int half = lane >> 4, n = lane & 15;
    int ch = warp * 2 + half;
    int d = d0 + ch;

    float An = -expf(alogs[(k * 128 + d) * 16 + n]);
    int dl = t & 7, lq = t >> 3;
    float4 w4 = *reinterpret_cast<const float4*>(&dtw[(k * 128 + d0 + dl) * 4]);
    float tb = dtb[k * 128 + d0 + dl];

    const float* xd = g_xdbl + bk * 36 * 1024;
    float h = c1 ? g_q[(bk * 128 + d) * 16 + n] : 0.f;

    for (int sc = 0; sc < 8; sc++) {
        int gl0 = c1 * 512 + sc * 64;
        #pragma unroll
        for (int i = 0; i < 16; i++) {
            int idx = i * 128 + t; int c = idx >> 6, l = idx & 63;
            s_bc[c * 65 + l] = xd[(4 + c) * 1024 + gl0 + l];
        }
        #pragma unroll
        for (int i = 0; i < 2; i++) {
            int idx = i * 128 + t; int r = idx >> 6, l = idx & 63;
            s_dts[r * 68 + l] = xd[r * 1024 + gl0 + l];
        }
        __syncthreads();
        dd_compute(s_dd, s_dts, b, k, gl0, dl, lq, d0, w4, tb);
        __syncthreads();
        #pragma unroll 4
        for (int l = 0; l < 64; l++) {
            float2 dd = s_dd[ch * 66 + l];
            float e = __expf(dd.x * An);
            float Bn = s_bc[n * 65 + l];
            float Cn = s_bc[(16 + n) * 65 + l];
            h = h * e + dd.y * Bn;
            float yv = h * Cn;
            yv += __shfl_xor_sync(0xffffffffu, yv, 8);
            yv += __shfl_xor_sync(0xffffffffu, yv, 4);
            yv += __shfl_xor_sync(0xffffffffu, yv, 2);
            yv += __shfl_xor_sync(0xffffffffu, yv, 1);
            if (n == 0) s_y[ch * 66 + l] = yv;
        }
        __syncthreads();
        #pragma unroll
        for (int i = 0; i < 4; i++) {
            int l = lq + i * 16;
            g_ys[(bk * 1024 + gl0 + l) * 128 + d0 + dl] = s_y[dl * 66 + l];
        }
        __syncthreads();
    }
}

// ---------------- K5: combine 4 dirs + D*x + LN + gate + out_proj + residual + LN + z_mamba ----------------
__global__ __launch_bounds__(128) void k5_back(
    const float* __restrict__ Ds, const float* __restrict__ ong,
    const float* __restrict__ onb, const float* __restrict__ opw,
    const float* __restrict__ mg, const float* __restrict__ mb)
{
    __shared__ float s_y[128];
    __shared__ float s_red[8];
    __shared__ float s_st[4];
    int b = blockIdx.x >> 10, p = blockIdx.x & 1023;
    int tp = (p & 31) * 32 + (p >> 5);
    int t = threadIdx.x, d = t;
    int b4 = b * 4;
    float y = g_ys[((b4 + 0) * 1024 + p) * 128 + d]
            + g_ys[((b4 + 2) * 1024 + (1023 - p)) * 128 + d]
            + g_ys[((b4 + 1) * 1024 + tp) * 128 + d]
            + g_ys[((b4 + 3) * 1024 + (1023 - tp)) * 128 + d];
    float sds = Ds[d] + Ds[128 + d] + Ds[256 + d] + Ds[384 + d];
    y += sds * g_x1s[(b * 1024 + p) * 128 + d];

    float s1 = y, s2 = y * y;
    #pragma unroll
    for (int o = 16; o; o >>= 1) {
        s1 += __shfl_xor_sync(0xffffffffu, s1, o);
        s2 += __shfl_xor_sync(0xffffffffu, s2, o);
    }
    if ((t & 31) == 0) { s_red[t >> 5] = s1; s_red[4 + (t >> 5)] = s2; }
    __syncthreads();
    if (t == 0) {
        float a = s_red[0] + s_red[1] + s_red[2] + s_red[3];
        float q = s_red[4] + s_red[5] + s_red[6] + s_red[7];
        float mu = a * (1.f / 128.f);
        float var = q * (1.f / 128.f) - mu * mu;
        s_st[0] = mu; s_st[1] = rsqrtf(var + EPS);
    }
    __syncthreads();
    float yn = (y - s_st[0]) * s_st[1] * ong[d] + onb[d];
    yn *= g_zs[(b * 1024 + p) * 128 + d];
    s_y[d] = yn;
    __syncthreads();

    float xm = 0.f;
    if (t < 64) {
        float acc = 0.f;
        const float4* w4 = reinterpret_cast<const float4*>(opw + t * 128);
        const float4* y4 = reinterpret_cast<const float4*>(s_y);
        #pragma unroll 8
        for (int i = 0; i < 32; i++) {
            float4 a = y4[i], ww = __ldg(&w4[i]);
            acc += a.x * ww.x + a.y * ww.y + a.z * ww.z + a.w * ww.w;
        }
        xm = g_x[(b * 1024 + p) * 64 + t] + acc;
    }
    float s1b = (t < 64) ? xm : 0.f, s2b = (t < 64) ? xm * xm : 0.f;
    #pragma unroll
    for (int o = 16; o; o >>= 1) {
        s1b += __shfl_xor_sync(0xffffffffu, s1b, o);
        s2b += __shfl_xor_sync(0xffffffffu, s2b, o);
    }
    if ((t & 31) == 0) { s_red[t >> 5] = s1b; s_red[4 + (t >> 5)] = s2b; }
    __syncthreads();
    if (t == 0) {
        float a = s_red[0] + s_red[1];
        float q = s_red[4] + s_red[5];
        float mu = a * (1.f / 64.f);
        float var = q * (1.f / 64.f) - mu * mu;
        s_st[2] = mu; s_st[3] = rsqrtf(var + EPS);
    }
    __syncthreads();
    if (t < 64) {
        float v = (xm - s_st[2]) * s_st[3] * mg[t] + mb[t];
        atomicAdd(&g_zj[b * 576 + 512 + t], v * (1.f / 1024.f));
    }
}

// ---------------- K6: joint-embed MLP head (warp-coalesced) ----------------
__global__ __launch_bounds__(256) void k6_head(
    const float* __restrict__ w1, const float* __restrict__ g1,
    const float* __restrict__ b1, const float* __restrict__ m1,
    const float* __restrict__ v1, const float* __restrict__ w2)
{
    __shared__ float s_z[576];
    __shared__ float s_h[64];
    int b = blockIdx.x, t = threadIdx.x;
    int warp = t >> 5, lane = t & 31;
    for (int i = t; i < 576; i += 256) s_z[i] = g_zj[b * 576 + i];
    __syncthreads();

    #pragma unroll
    for (int mi = 0; mi < 8; mi++) {
        int m = warp * 8 + mi;
        float acc = 0.f;
        #pragma unroll 6
        for (int jk = 0; jk < 18; jk++) {
            int j = lane + jk * 32;
            acc += s_z[j] * __ldg(&w1[m * 576 + j]);
        }
        #pragma unroll
        for (int o = 16; o; o >>= 1) acc += __shfl_xor_sync(0xffffffffu, acc, o);
        if (lane == 0) {
            float hm = (acc - m1[m]) * rsqrtf(v1[m] + EPS) * g1[m] + b1[m];
            s_h[m] = fmaxf(hm, 0.f);
        }
    }
    __syncthreads();

    float zl0 = s_h[lane], zl1 = s_h[lane + 32];
    for (int oi = 0; oi < 64; oi++) {
        int o = warp * 64 + oi;
        float acc = zl0 * __ldg(&w2[o * 64 + lane]) + zl1 * __ldg(&w2[o * 64 + lane + 32]);
        #pragma unroll
        for (int q = 16; q; q >>= 1) acc += __shfl_xor_sync(0xffffffffu, acc, q);
        if (lane == 0) g_wgt[b * 512 + o] = 1.f / (1.f + __expf(-acc));
    }
}

// ---------------- K7: out = rgb*(1+wr) + dem*(1+wd) ----------------
__global__ __launch_bounds__(256) void k7_out(const float* __restrict__ rgb,
                                              const float* __restrict__ dem,
                                              float* __restrict__ out) {
    int idx = blockIdx.x * 256 + threadIdx.x;
    int b = idx >> 18;
    int c = (idx >> 10) & 255;
    float wr = g_wgt[b * 512 + c];
    float wd = g_wgt[b * 512 + 256 + c];
    out[idx] = rgb[idx] * (1.f + wr) + dem[idx] * (1.f + wd);
}

// ---------------- launch ----------------
extern "C" void kernel_launch(void* const* d_in, const int* in_sizes, int n_in,
                              void* d_out, int out_size) {
    const float* rgb   = (const float*)d_in[0];
    const float* dem   = (const float*)d_in[1];
    const float* wred  = (const float*)d_in[2];
    const float* bnr_g = (const float*)d_in[3];
    const float* bnr_b = (const float*)d_in[4];
    const float* bnr_m = (const float*)d_in[5];
    const float* bnr_v = (const float*)d_in[6];
    const float* ln1_g = (const float*)d_in[7];
    const float* ln1_b = (const float*)d_in[8];
    const float* ipw   = (const float*)d_in[9];
    const float* convw = (const float*)d_in[10];
    const float* convb = (const float*)d_in[11];
    const float* xpw   = (const float*)d_in[12];
    const float* dtw   = (const float*)d_in[13];
    const float* dtb   = (const float*)d_in[14];
    const float* alogs = (const float*)d_in[15];
    const float* Ds    = (const float*)d_in[16];
    const float* on_g  = (const float*)d_in[17];
    const float* on_b  = (const float*)d_in[18];
    const float* opw   = (const float*)d_in[19];
    const float* mno_g = (const float*)d_in[20];
    const float* mno_b = (const float*)d_in[21];
    const float* je_w1 = (const float*)d_in[22];
    const float* bn1_g = (const float*)d_in[23];
    const float* bn1_b = (const float*)d_in[24];
    const float* bn1_m = (const float*)d_in[25];
    const float* bn1_v = (const float*)d_in[26];
    const float* je_w2 = (const float*)d_in[27];
    float* out = (float*)d_out;

    k0_means<<<512, 256>>>(rgb, dem);
    k1_front<<<512, 256>>>(rgb, dem, wred, bnr_g, bnr_b, bnr_m, bnr_v,
                           ln1_g, ln1_b, ipw);
    k2_conv<<<8192, 128>>>(convw, convb);
    k3_xdbl<<<512, 128>>>(xpw);
    k4a_carry<<<512, 128>>>(alogs, dtw, dtb);
    k4b_scan<<<1024, 128>>>(alogs, dtw, dtb);
    k5_back<<<8192, 128>>>(Ds, on_g, on_b, opw, mno_g, mno_b);
    k6_head<<<8, 256>>>(je_w1, bn1_g, bn1_b, bn1_m, bn1_v, je_w2);
    k7_out<<<8192, 256>>>(rgb, dem, out);
}

// round 15
// speedup vs baseline: 1.0762x; 1.0762x over previous
#include <cuda_runtime.h>
#include <math.h>

#define EPS 1e-5f

// ---------------- scratch (device globals; no allocation) ----------------
__device__ float g_x[8*1024*64];        // BN'd x, NHWC (residual)
__device__ float g_x1[8*1024*128];      // in_proj x1 (pre-conv), NHWC
__device__ float g_zs[8*1024*128];      // silu(z), NHWC
__device__ float g_x1s[8*1024*128];     // conv+silu output, NHWC
__device__ float g_xdbl[8*4*36*1024];   // (b,k,c,l): rows 0-3 dts, 4-19 B, 20-35 C
__device__ float g_ys[8*4*1024*128];    // (b,k,l,d)
__device__ float g_q[32*128*16];        // carry h at l=512 per (bk,d,n)
__device__ int   g_flag[512];           // carry-ready flags, cleared by k3
__device__ float g_zj[8*576];           // [z_rgb(256), z_dem(256), z_mamba(64)]
__device__ float g_wgt[8*512];

// scan-order index l (direction k) -> spatial position p
__device__ __forceinline__ int perm_idx(int k, int l) {
    int m = (k >= 2) ? (1023 - l) : l;
    if (k & 1) m = (m & 31) * 32 + (m >> 5);
    return m;
}

// ---------------- K0: channel means of rgb/dem + zero z_mamba ----------------
__global__ __launch_bounds__(256) void k0_means(const float* __restrict__ rgb,
                                                const float* __restrict__ dem) {
    int t = threadIdx.x, blk = blockIdx.x;
    if (blk == 0) {
        #pragma unroll
        for (int q = 0; q < 2; q++) {
            int i = q * 256 + t;               // 0..511: all 8 batches x 64
            g_zj[(i >> 6) * 576 + 512 + (i & 63)] = 0.f;
        }
    }
    int gw = blk * 8 + (t >> 5);
    int lane = t & 31;
    const float* src = (gw < 2048) ? rgb : dem;
    int cc = gw & 2047;
    const float* ptr = src + cc * 1024;
    float s = 0.f;
    #pragma unroll
    for (int i = 0; i < 32; i++) s += ptr[lane + i * 32];
    #pragma unroll
    for (int o = 16; o; o >>= 1) s += __shfl_xor_sync(0xffffffffu, s, o);
    if (lane == 0) {
        int b = cc >> 8, c = cc & 255;
        g_zj[b * 576 + ((gw < 2048) ? c : 256 + c)] = s * (1.f / 1024.f);
    }
}

// ---------------- K1: (rgb+dem) -> reduce GEMM -> BN -> LN -> in_proj (R7) ----------------
__global__ __launch_bounds__(256) void k1_front(
    const float* __restrict__ rgb, const float* __restrict__ dem,
    const float* __restrict__ wred,
    const float* __restrict__ bg, const float* __restrict__ bb,
    const float* __restrict__ bm, const float* __restrict__ bv,
    const float* __restrict__ lg, const float* __restrict__ lb,
    const float* __restrict__ ipw)
{
    __shared__ float s_buf[8448];
    __shared__ float s_a[2080];
    __shared__ float s_r1[256], s_r2[256];
    __shared__ float s_mu[32], s_rs[32];

    int t = threadIdx.x;
    int b = blockIdx.x >> 5, h = blockIdx.x & 31;

    const float* rp = rgb + b * 262144 + h * 32;
    const float* dp = dem + b * 262144 + h * 32;
    #pragma unroll 4
    for (int i = 0; i < 32; i++) {
        int idx = i * 256 + t; int c = idx >> 5, w = idx & 31;
        s_buf[c * 32 + w] = rp[c * 1024 + w] + dp[c * 1024 + w];
    }
    __syncthreads();

    int w = t & 31, og = (t >> 5) * 8;
    float acc[8];
    #pragma unroll
    for (int j = 0; j < 8; j++) acc[j] = 0.f;

    for (int cb = 0; cb < 256; cb += 32) {
        __syncthreads();
        #pragma unroll
        for (int i = 0; i < 8; i++) {
            int idx = i * 256 + t; int c2 = idx & 31, o2 = idx >> 5;
            s_a[c2 * 64 + o2] = wred[o2 * 256 + cb + c2];
        }
        __syncthreads();
        #pragma unroll 8
        for (int c2 = 0; c2 < 32; c2++) {
            float v = s_buf[(cb + c2) * 32 + w];
            float4 w0 = *reinterpret_cast<const float4*>(&s_a[c2 * 64 + og]);
            float4 w1 = *reinterpret_cast<const float4*>(&s_a[c2 * 64 + og + 4]);
            acc[0] += v * w0.x; acc[1] += v * w0.y; acc[2] += v * w0.z; acc[3] += v * w0.w;
            acc[4] += v * w1.x; acc[5] += v * w1.y; acc[6] += v * w1.z; acc[7] += v * w1.w;
        }
    }

    float xr[8]; float s1 = 0.f, s2 = 0.f;
    #pragma unroll
    for (int j = 0; j < 8; j++) {
        int o = og + j;
        float v = (acc[j] - bm[o]) * rsqrtf(bv[o] + EPS) * bg[o] + bb[o];
        xr[j] = v; s1 += v; s2 += v * v;
    }
    int p = h * 32 + w;
    float* gx = g_x + (b * 1024 + p) * 64 + og;
    *reinterpret_cast<float4*>(gx)     = make_float4(xr[0], xr[1], xr[2], xr[3]);
    *reinterpret_cast<float4*>(gx + 4) = make_float4(xr[4], xr[5], xr[6], xr[7]);
    s_r1[(t >> 5) * 32 + w] = s1; s_r2[(t >> 5) * 32 + w] = s2;
    __syncthreads();
    if (t < 32) {
        float a = 0.f, q = 0.f;
        #pragma unroll
        for (int j = 0; j < 8; j++) { a += s_r1[j * 32 + t]; q += s_r2[j * 32 + t]; }
        float mu = a * (1.f / 64.f);
        float var = q * (1.f / 64.f) - mu * mu;
        s_mu[t] = mu; s_rs[t] = rsqrtf(var + EPS);
    }
    __syncthreads();
    {
        float mu = s_mu[w], rs = s_rs[w];
        #pragma unroll
        for (int j = 0; j < 8; j++) {
            int o = og + j;
            s_a[w * 65 + o] = (xr[j] - mu) * rs * lg[o] + lb[o];
        }
    }
    __syncthreads();

    int jb = (t >> 5) * 16;
    for (int pj = 0; pj < 2; pj++) {
        #pragma unroll 4
        for (int i = 0; i < 32; i++) {
            int idx = i * 256 + t; int o = idx & 63, j = idx >> 6;
            s_buf[o * 132 + j] = ipw[(pj * 128 + j) * 64 + o];
        }
        __syncthreads();
        float a2[16];
        #pragma unroll
        for (int j = 0; j < 16; j++) a2[j] = 0.f;
        #pragma unroll 4
        for (int o = 0; o < 64; o++) {
            float xv = s_a[w * 65 + o];
            const float* wr0 = &s_buf[o * 132 + jb];
            float4 q0 = *reinterpret_cast<const float4*>(wr0);
            float4 q1 = *reinterpret_cast<const float4*>(wr0 + 4);
            float4 q2 = *reinterpret_cast<const float4*>(wr0 + 8);
            float4 q3 = *reinterpret_cast<const float4*>(wr0 + 12);
            a2[0] += xv * q0.x; a2[1] += xv * q0.y; a2[2] += xv * q0.z; a2[3] += xv * q0.w;
            a2[4] += xv * q1.x; a2[5] += xv * q1.y; a2[6] += xv * q1.z; a2[7] += xv * q1.w;
            a2[8] += xv * q2.x; a2[9] += xv * q2.y; a2[10] += xv * q2.z; a2[11] += xv * q2.w;
            a2[12] += xv * q3.x; a2[13] += xv * q3.y; a2[14] += xv * q3.z; a2[15] += xv * q3.w;
        }
        if (pj == 1) {
            #pragma unroll
            for (int j = 0; j < 16; j++) a2[j] = a2[j] / (1.f + __expf(-a2[j]));
        }
        float* dst = (pj == 0 ? g_x1 : g_zs) + (b * 1024 + p) * 128 + jb;
        *reinterpret_cast<float4*>(dst)      = make_float4(a2[0], a2[1], a2[2], a2[3]);
        *reinterpret_cast<float4*>(dst + 4)  = make_float4(a2[4], a2[5], a2[6], a2[7]);
        *reinterpret_cast<float4*>(dst + 8)  = make_float4(a2[8], a2[9], a2[10], a2[11]);
        *reinterpret_cast<float4*>(dst + 12) = make_float4(a2[12], a2[13], a2[14], a2[15]);
        __syncthreads();
    }
}

// ---------------- K2: depthwise 3x3 conv + bias + silu (NHWC, R7) ----------------
__global__ __launch_bounds__(128) void k2_conv(const float* __restrict__ cw,
                                               const float* __restrict__ cb) {
    int b = blockIdx.x >> 10, p = blockIdx.x & 1023;
    int h = p >> 5, w = p & 31, d = threadIdx.x;
    float s = cb[d];
    #pragma unroll
    for (int i = -1; i <= 1; i++) {
        int hh = h + i; if ((unsigned)hh >= 32u) continue;
        #pragma unroll
        for (int j = -1; j <= 1; j++) {
            int ww = w + j; if ((unsigned)ww >= 32u) continue;
            s += g_x1[(b * 1024 + hh * 32 + ww) * 128 + d] *
                 __ldg(&cw[d * 9 + (i + 1) * 3 + (j + 1)]);
        }
    }
    s = s / (1.f + __expf(-s));
    g_x1s[(b * 1024 + p) * 128 + d] = s;
}

// ---------------- K3: x_dbl = xs @ x_proj_w^T (R7) + clear carry flags ----------------
__global__ __launch_bounds__(128) void k3_xdbl(const float* __restrict__ xpw) {
    __shared__ float s_u[64 * 132];   // 33792 B
    int blk = blockIdx.x; int bk = blk >> 4, lt = blk & 15;
    int b = bk >> 2, k = bk & 3; int l0 = lt * 64;
    int t = threadIdx.x;
    if (t == 0) g_flag[blk] = 0;      // clear this run's carry flag (prev k4 long done)
    #pragma unroll 4
    for (int l = 0; l < 64; l++)
        s_u[l * 132 + t] = g_x1s[(b * 1024 + perm_idx(k, l0 + l)) * 128 + t];
    __syncthreads();
    int lsub = t & 31, cg = t >> 5;
    float acc0[9], acc1[9];
    #pragma unroll
    for (int j = 0; j < 9; j++) { acc0[j] = 0.f; acc1[j] = 0.f; }
    const float4* urow0 = reinterpret_cast<const float4*>(&s_u[lsub * 132]);
    const float4* urow1 = reinterpret_cast<const float4*>(&s_u[(lsub + 32) * 132]);
    const float4* wbase = reinterpret_cast<const float4*>(xpw + (k * 36 + cg * 9) * 128);
    #pragma unroll 4
    for (int d4 = 0; d4 < 32; d4++) {
        float4 u0 = urow0[d4];
        float4 u1 = urow1[d4];
        #pragma unroll
        for (int j = 0; j < 9; j++) {
            float4 wv = __ldg(&wbase[j * 32 + d4]);
            acc0[j] += u0.x * wv.x + u0.y * wv.y + u0.z * wv.z + u0.w * wv.w;
            acc1[j] += u1.x * wv.x + u1.y * wv.y + u1.z * wv.z + u1.w * wv.w;
        }
    }
    float* dst = g_xdbl + bk * 36 * 1024 + l0;
    #pragma unroll
    for (int j = 0; j < 9; j++) {
        dst[(cg * 9 + j) * 1024 + lsub]      = acc0[j];
        dst[(cg * 9 + j) * 1024 + lsub + 32] = acc1[j];
    }
}

// ================= K4 fused: carry (A) + emit chunks (B0/B1) in ONE launch =================
// blocks [0,512): A — scan l<512, carry only, write g_q, set g_flag.
// blocks [512,1024): B0 — chunk-0 emit (no dependency).
// blocks [1024,1536): B1 — chunk-1 emit; spin on g_flag, seed h from g_q.
__device__ __forceinline__ void dd_compute(
    float2* s_dd, const float* s_dts, int b, int k, int gl0,
    int dl, int lq, int d0, float4 w4, float tb)
{
    #pragma unroll
    for (int i = 0; i < 4; i++) {
        int l = lq + i * 16;
        float x = tb + s_dts[l] * w4.x + s_dts[68 + l] * w4.y
                     + s_dts[136 + l] * w4.z + s_dts[204 + l] * w4.w;
        float e = __expf(x);
        float delta = (x > 20.f) ? x : __logf(1.f + e);
        float u = g_x1s[(b * 1024 + perm_idx(k, gl0 + l)) * 128 + d0 + dl];
        s_dd[dl * 66 + l] = make_float2(delta, delta * u);
    }
}

__global__ __launch_bounds__(128) void k4_fused(
    const float* __restrict__ alogs,
    const float* __restrict__ dtw, const float* __restrict__ dtb)
{
    __shared__ float s_bc[32 * 65];
    __shared__ float s_dts[4 * 68];
    __shared__ float2 s_dd[8 * 66];
    __shared__ float s_y[8 * 66];

    int blk = blockIdx.x;
    int role = blk >> 9;                 // 0=A, 1=B0, 2=B1
    int idx = blk & 511;                 // (bk, dg)
    int bk = idx >> 4, dg = idx & 15;
    int b = bk >> 2, k = bk & 3;
    int d0 = dg * 8;
    int t = threadIdx.x, warp = t >> 5, lane = t & 31;
    int half = lane >> 4, n = lane & 15;
    int ch = warp * 2 + half;
    int d = d0 + ch;

    float An = -expf(alogs[(k * 128 + d) * 16 + n]);
    int dl = t & 7, lq = t >> 3;
    float4 w4 = *reinterpret_cast<const float4*>(&dtw[(k * 128 + d0 + dl) * 4]);
    float tb = dtb[k * 128 + d0 + dl];
    const float* xd = g_xdbl + bk * 36 * 1024;

    if (role == 0) {
        // ---- A: carry for l in [0,512) ----
        float h = 0.f;
        for (int sc = 0; sc < 8; sc++) {
            int gl0 = sc * 64;
            #pragma unroll
            for (int i = 0; i < 8; i++) {
                int ii = i * 128 + t; int c = ii >> 6, l = ii & 63;
                s_bc[c * 65 + l] = xd[(4 + c) * 1024 + gl0 + l];
            }
            #pragma unroll
            for (int i = 0; i < 2; i++) {
                int ii = i * 128 + t; int r = ii >> 6, l = ii & 63;
                s_dts[r * 68 + l] = xd[r * 1024 + gl0 + l];
            }
            __syncthreads();
            dd_compute(s_dd, s_dts, b, k, gl0, dl, lq, d0, w4, tb);
            __syncthreads();
            #pragma unroll 4
            for (int l = 0; l < 64; l++) {
                float2 dd = s_dd[ch * 66 + l];
                float e = __expf(dd.x * An);
                float Bn = s_bc[n * 65 + l];
                h = h * e + dd.y * Bn;
            }
            __syncthreads();
        }
        g_q[(bk * 128 + d) * 16 + n] = h;
        __syncthreads();
        if (t == 0) {
            __threadfence();
            atomicExch(&g_flag[idx], 1);
        }
        return;
    }

    // ---- B0/B1: emit chunk c1 ----
    int c1 = role - 1;
    float h = 0.f;
    if (c1 == 1) {
        if (t == 0) {
            while (atomicAdd(&g_flag[idx], 0) == 0) { }
        }
        __syncthreads();
        __threadfence();
        h = g_q[(bk * 128 + d) * 16 + n];
    }

    for (int sc = 0; sc < 8; sc++) {
        int gl0 = c1 * 512 + sc * 64;
        #pragma unroll
        for (int i = 0; i < 16; i++) {
            int ii = i * 128 + t; int c = ii >> 6, l = ii & 63;
            s_bc[c * 65 + l] = xd[(4 + c) * 1024 + gl0 + l];
        }
        #pragma unroll
        for (int i = 0; i < 2; i++) {
            int ii = i * 128 + t; int r = ii >> 6, l = ii & 63;
            s_dts[r * 68 + l] = xd[r * 1024 + gl0 + l];
        }
        __syncthreads();
        dd_compute(s_dd, s_dts, b, k, gl0, dl, lq, d0, w4, tb);
        __syncthreads();
        #pragma unroll 4
        for (int l = 0; l < 64; l++) {
            float2 dd = s_dd[ch * 66 + l];
            float e = __expf(dd.x * An);
            float Bn = s_bc[n * 65 + l];
            float Cn = s_bc[(16 + n) * 65 + l];
            h = h * e + dd.y * Bn;
            float yv = h * Cn;
            yv += __shfl_xor_sync(0xffffffffu, yv, 8);
            yv += __shfl_xor_sync(0xffffffffu, yv, 4);
            yv += __shfl_xor_sync(0xffffffffu, yv, 2);
            yv += __shfl_xor_sync(0xffffffffu, yv, 1);
            if (n == 0) s_y[ch * 66 + l] = yv;
        }
        __syncthreads();
        #pragma unroll
        for (int i = 0; i < 4; i++) {
            int l = lq + i * 16;
            g_ys[(bk * 1024 + gl0 + l) * 128 + d0 + dl] = s_y[dl * 66 + l];
        }
        __syncthreads();
    }
}

// ---------------- K5: combine 4 dirs + D*x + LN + gate + out_proj + residual + LN + z_mamba (R7) ----------------
__global__ __launch_bounds__(128) void k5_back(
    const float* __restrict__ Ds, const float* __restrict__ ong,
    const float* __restrict__ onb, const float* __restrict__ opw,
    const float* __restrict__ mg, const float* __restrict__ mb)
{
    __shared__ float s_y[128];
    __shared__ float s_red[8];
    __shared__ float s_st[4];
    int b = blockIdx.x >> 10, p = blockIdx.x & 1023;
    int tp = (p & 31) * 32 + (p >> 5);
    int t = threadIdx.x, d = t;
    int b4 = b * 4;
    float y = g_ys[((b4 + 0) * 1024 + p) * 128 + d]
            + g_ys[((b4 + 2) * 1024 + (1023 - p)) * 128 + d]
            + g_ys[((b4 + 1) * 1024 + tp) * 128 + d]
            + g_ys[((b4 + 3) * 1024 + (1023 - tp)) * 128 + d];
    float sds = Ds[d] + Ds[128 + d] + Ds[256 + d] + Ds[384 + d];
    y += sds * g_x1s[(b * 1024 + p) * 128 + d];

    float s1 = y, s2 = y * y;
    #pragma unroll
    for (int o = 16; o; o >>= 1) {
        s1 += __shfl_xor_sync(0xffffffffu, s1, o);
        s2 += __shfl_xor_sync(0xffffffffu, s2, o);
    }
    if ((t & 31) == 0) { s_red[t >> 5] = s1; s_red[4 + (t >> 5)] = s2; }
    __syncthreads();
    if (t == 0) {
        float a = s_red[0] + s_red[1] + s_red[2] + s_red[3];
        float q = s_red[4] + s_red[5] + s_red[6] + s_red[7];
        float mu = a * (1.f / 128.f);
        float var = q * (1.f / 128.f) - mu * mu;
        s_st[0] = mu; s_st[1] = rsqrtf(var + EPS);
    }
    __syncthreads();
    float yn = (y - s_st[0]) * s_st[1] * ong[d] + onb[d];
    yn *= g_zs[(b * 1024 + p) * 128 + d];
    s_y[d] = yn;
    __syncthreads();

    float xm = 0.f;
    if (t < 64) {
        float acc = 0.f;
        const float4* w4 = reinterpret_cast<const float4*>(opw + t * 128);
        const float4* y4 = reinterpret_cast<const float4*>(s_y);
        #pragma unroll 8
        for (int i = 0; i < 32; i++) {
            float4 a = y4[i], ww = __ldg(&w4[i]);
            acc += a.x * ww.x + a.y * ww.y + a.z * ww.z + a.w * ww.w;
        }
        xm = g_x[(b * 1024 + p) * 64 + t] + acc;
    }
    float s1b = (t < 64) ? xm : 0.f, s2b = (t < 64) ? xm * xm : 0.f;
    #pragma unroll
    for (int o = 16; o; o >>= 1) {
        s1b += __shfl_xor_sync(0xffffffffu, s1b, o);
        s2b += __shfl_xor_sync(0xffffffffu, s2b, o);
    }
    if ((t & 31) == 0) { s_red[t >> 5] = s1b; s_red[4 + (t >> 5)] = s2b; }
    __syncthreads();
    if (t == 0) {
        float a = s_red[0] + s_red[1];
        float q = s_red[4] + s_red[5];
        float mu = a * (1.f / 64.f);
        float var = q * (1.f / 64.f) - mu * mu;
        s_st[2] = mu; s_st[3] = rsqrtf(var + EPS);
    }
    __syncthreads();
    if (t < 64) {
        float v = (xm - s_st[2]) * s_st[3] * mg[t] + mb[t];
        atomicAdd(&g_zj[b * 576 + 512 + t], v * (1.f / 1024.f));
    }
}

// ---------------- K6: joint-embed MLP head (warp-coalesced, R7) ----------------
__global__ __launch_bounds__(256) void k6_head(
    const float* __restrict__ w1, const float* __restrict__ g1,
    const float* __restrict__ b1, const float* __restrict__ m1,
    const float* __restrict__ v1, const float* __restrict__ w2)
{
    __shared__ float s_z[576];
    __shared__ float s_h[64];
    int b = blockIdx.x, t = threadIdx.x;
    int warp = t >> 5, lane = t & 31;
    for (int i = t; i < 576; i += 256) s_z[i] = g_zj[b * 576 + i];
    __syncthreads();

    #pragma unroll
    for (int mi = 0; mi < 8; mi++) {
        int m = warp * 8 + mi;
        float acc = 0.f;
        #pragma unroll 6
        for (int jk = 0; jk < 18; jk++) {
            int j = lane + jk * 32;
            acc += s_z[j] * __ldg(&w1[m * 576 + j]);
        }
        #pragma unroll
        for (int o = 16; o; o >>= 1) acc += __shfl_xor_sync(0xffffffffu, acc, o);
        if (lane == 0) {
            float hm = (acc - m1[m]) * rsqrtf(v1[m] + EPS) * g1[m] + b1[m];
            s_h[m] = fmaxf(hm, 0.f);
        }
    }
    __syncthreads();

    float zl0 = s_h[lane], zl1 = s_h[lane + 32];
    for (int oi = 0; oi < 64; oi++) {
        int o = warp * 64 + oi;
        float acc = zl0 * __ldg(&w2[o * 64 + lane]) + zl1 * __ldg(&w2[o * 64 + lane + 32]);
        #pragma unroll
        for (int q = 16; q; q >>= 1) acc += __shfl_xor_sync(0xffffffffu, acc, q);
        if (lane == 0) g_wgt[b * 512 + o] = 1.f / (1.f + __expf(-acc));
    }
}

// ---------------- K7: out = rgb*(1+wr) + dem*(1+wd) ----------------
__global__ __launch_bounds__(256) void k7_out(const float* __restrict__ rgb,
                                              const float* __restrict__ dem,
                                              float* __restrict__ out) {
    int idx = blockIdx.x * 256 + threadIdx.x;
    int b = idx >> 18;
    int c = (idx >> 10) & 255;
    float wr = g_wgt[b * 512 + c];
    float wd = g_wgt[b * 512 + 256 + c];
    out[idx] = rgb[idx] * (1.f + wr) + dem[idx] * (1.f + wd);
}

// ---------------- launch ----------------
extern "C" void kernel_launch(void* const* d_in, const int* in_sizes, int n_in,
                              void* d_out, int out_size) {
    const float* rgb   = (const float*)d_in[0];
    const float* dem   = (const float*)d_in[1];
    const float* wred  = (const float*)d_in[2];
    const float* bnr_g = (const float*)d_in[3];
    const float* bnr_b = (const float*)d_in[4];
    const float* bnr_m = (const float*)d_in[5];
    const float* bnr_v = (const float*)d_in[6];
    const float* ln1_g = (const float*)d_in[7];
    const float* ln1_b = (const float*)d_in[8];
    const float* ipw   = (const float*)d_in[9];
    const float* convw = (const float*)d_in[10];
    const float* convb = (const float*)d_in[11];
    const float* xpw   = (const float*)d_in[12];
    const float* dtw   = (const float*)d_in[13];
    const float* dtb   = (const float*)d_in[14];
    const float* alogs = (const float*)d_in[15];
    const float* Ds    = (const float*)d_in[16];
    const float* on_g  = (const float*)d_in[17];
    const float* on_b  = (const float*)d_in[18];
    const float* opw   = (const float*)d_in[19];
    const float* mno_g = (const float*)d_in[20];
    const float* mno_b = (const float*)d_in[21];
    const float* je_w1 = (const float*)d_in[22];
    const float* bn1_g = (const float*)d_in[23];
    const float* bn1_b = (const float*)d_in[24];
    const float* bn1_m = (const float*)d_in[25];
    const float* bn1_v = (const float*)d_in[26];
    const float* je_w2 = (const float*)d_in[27];
    float* out = (float*)d_out;

    k0_means<<<512, 256>>>(rgb, dem);
    k1_front<<<256, 256>>>(rgb, dem, wred, bnr_g, bnr_b, bnr_m, bnr_v,
                           ln1_g, ln1_b, ipw);
    k2_conv<<<8192, 128>>>(convw, convb);
    k3_xdbl<<<512, 128>>>(xpw);
    k4_fused<<<1536, 128>>>(alogs, dtw, dtb);
    k5_back<<<8192, 128>>>(Ds, on_g, on_b, opw, mno_g, mno_b);
    k6_head<<<8, 256>>>(je_w1, bn1_g, bn1_b, bn1_m, bn1_v, je_w2);
    k7_out<<<8192, 256>>>(rgb, dem, out);
}

// round 16
// speedup vs baseline: 1.1333x; 1.0531x over previous
#include <cuda_runtime.h>
#include <math.h>

#define EPS 1e-5f

// ---------------- scratch (device globals; no allocation) ----------------
__device__ float g_x[8*1024*64];        // BN'd x, NHWC (residual)
__device__ float g_x1[8*1024*128];      // in_proj x1 (pre-conv), NHWC
__device__ float g_zs[8*1024*128];      // silu(z), NHWC
__device__ float g_x1s[8*1024*128];     // conv+silu output, NHWC
__device__ float g_xdbl[8*4*36*1024];   // (b,k,c,l): rows 0-3 dts, 4-19 B, 20-35 C
__device__ float g_ys[8*4*1024*128];    // (b,k,l,d)
__device__ float g_q[32*128*16];        // carry h at l=512 per (bk,d,n)
__device__ int   g_flag[256];           // carry-ready flags, cleared by k3
__device__ float g_zj[8*576];           // [z_rgb(256), z_dem(256), z_mamba(64)]
__device__ float g_wgt[8*512];

// scan-order index l (direction k) -> spatial position p
__device__ __forceinline__ int perm_idx(int k, int l) {
    int m = (k >= 2) ? (1023 - l) : l;
    if (k & 1) m = (m & 31) * 32 + (m >> 5);
    return m;
}

// ---------------- K0: channel means of rgb/dem + zero z_mamba ----------------
__global__ __launch_bounds__(256) void k0_means(const float* __restrict__ rgb,
                                                const float* __restrict__ dem) {
    int t = threadIdx.x, blk = blockIdx.x;
    if (blk == 0) {
        #pragma unroll
        for (int q = 0; q < 2; q++) {
            int i = q * 256 + t;               // 0..511: all 8 batches x 64
            g_zj[(i >> 6) * 576 + 512 + (i & 63)] = 0.f;
        }
    }
    int gw = blk * 8 + (t >> 5);
    int lane = t & 31;
    const float* src = (gw < 2048) ? rgb : dem;
    int cc = gw & 2047;
    const float* ptr = src + cc * 1024;
    float s = 0.f;
    #pragma unroll
    for (int i = 0; i < 32; i++) s += ptr[lane + i * 32];
    #pragma unroll
    for (int o = 16; o; o >>= 1) s += __shfl_xor_sync(0xffffffffu, s, o);
    if (lane == 0) {
        int b = cc >> 8, c = cc & 255;
        g_zj[b * 576 + ((gw < 2048) ? c : 256 + c)] = s * (1.f / 1024.f);
    }
}

// ---------------- K1: (rgb+dem) -> reduce GEMM -> BN -> LN -> in_proj (R7) ----------------
__global__ __launch_bounds__(256) void k1_front(
    const float* __restrict__ rgb, const float* __restrict__ dem,
    const float* __restrict__ wred,
    const float* __restrict__ bg, const float* __restrict__ bb,
    const float* __restrict__ bm, const float* __restrict__ bv,
    const float* __restrict__ lg, const float* __restrict__ lb,
    const float* __restrict__ ipw)
{
    __shared__ float s_buf[8448];
    __shared__ float s_a[2080];
    __shared__ float s_r1[256], s_r2[256];
    __shared__ float s_mu[32], s_rs[32];

    int t = threadIdx.x;
    int b = blockIdx.x >> 5, h = blockIdx.x & 31;

    const float* rp = rgb + b * 262144 + h * 32;
    const float* dp = dem + b * 262144 + h * 32;
    #pragma unroll 4
    for (int i = 0; i < 32; i++) {
        int idx = i * 256 + t; int c = idx >> 5, w = idx & 31;
        s_buf[c * 32 + w] = rp[c * 1024 + w] + dp[c * 1024 + w];
    }
    __syncthreads();

    int w = t & 31, og = (t >> 5) * 8;
    float acc[8];
    #pragma unroll
    for (int j = 0; j < 8; j++) acc[j] = 0.f;

    for (int cb = 0; cb < 256; cb += 32) {
        __syncthreads();
        #pragma unroll
        for (int i = 0; i < 8; i++) {
            int idx = i * 256 + t; int c2 = idx & 31, o2 = idx >> 5;
            s_a[c2 * 64 + o2] = wred[o2 * 256 + cb + c2];
        }
        __syncthreads();
        #pragma unroll 8
        for (int c2 = 0; c2 < 32; c2++) {
            float v = s_buf[(cb + c2) * 32 + w];
            float4 w0 = *reinterpret_cast<const float4*>(&s_a[c2 * 64 + og]);
            float4 w1 = *reinterpret_cast<const float4*>(&s_a[c2 * 64 + og + 4]);
            acc[0] += v * w0.x; acc[1] += v * w0.y; acc[2] += v * w0.z; acc[3] += v * w0.w;
            acc[4] += v * w1.x; acc[5] += v * w1.y; acc[6] += v * w1.z; acc[7] += v * w1.w;
        }
    }

    float xr[8]; float s1 = 0.f, s2 = 0.f;
    #pragma unroll
    for (int j = 0; j < 8; j++) {
        int o = og + j;
        float v = (acc[j] - bm[o]) * rsqrtf(bv[o] + EPS) * bg[o] + bb[o];
        xr[j] = v; s1 += v; s2 += v * v;
    }
    int p = h * 32 + w;
    float* gx = g_x + (b * 1024 + p) * 64 + og;
    *reinterpret_cast<float4*>(gx)     = make_float4(xr[0], xr[1], xr[2], xr[3]);
    *reinterpret_cast<float4*>(gx + 4) = make_float4(xr[4], xr[5], xr[6], xr[7]);
    s_r1[(t >> 5) * 32 + w] = s1; s_r2[(t >> 5) * 32 + w] = s2;
    __syncthreads();
    if (t < 32) {
        float a = 0.f, q = 0.f;
        #pragma unroll
        for (int j = 0; j < 8; j++) { a += s_r1[j * 32 + t]; q += s_r2[j * 32 + t]; }
        float mu = a * (1.f / 64.f);
        float var = q * (1.f / 64.f) - mu * mu;
        s_mu[t] = mu; s_rs[t] = rsqrtf(var + EPS);
    }
    __syncthreads();
    {
        float mu = s_mu[w], rs = s_rs[w];
        #pragma unroll
        for (int j = 0; j < 8; j++) {
            int o = og + j;
            s_a[w * 65 + o] = (xr[j] - mu) * rs * lg[o] + lb[o];
        }
    }
    __syncthreads();

    int jb = (t >> 5) * 16;
    for (int pj = 0; pj < 2; pj++) {
        #pragma unroll 4
        for (int i = 0; i < 32; i++) {
            int idx = i * 256 + t; int o = idx & 63, j = idx >> 6;
            s_buf[o * 132 + j] = ipw[(pj * 128 + j) * 64 + o];
        }
        __syncthreads();
        float a2[16];
        #pragma unroll
        for (int j = 0; j < 16; j++) a2[j] = 0.f;
        #pragma unroll 4
        for (int o = 0; o < 64; o++) {
            float xv = s_a[w * 65 + o];
            const float* wr0 = &s_buf[o * 132 + jb];
            float4 q0 = *reinterpret_cast<const float4*>(wr0);
            float4 q1 = *reinterpret_cast<const float4*>(wr0 + 4);
            float4 q2 = *reinterpret_cast<const float4*>(wr0 + 8);
            float4 q3 = *reinterpret_cast<const float4*>(wr0 + 12);
            a2[0] += xv * q0.x; a2[1] += xv * q0.y; a2[2] += xv * q0.z; a2[3] += xv * q0.w;
            a2[4] += xv * q1.x; a2[5] += xv * q1.y; a2[6] += xv * q1.z; a2[7] += xv * q1.w;
            a2[8] += xv * q2.x; a2[9] += xv * q2.y; a2[10] += xv * q2.z; a2[11] += xv * q2.w;
            a2[12] += xv * q3.x; a2[13] += xv * q3.y; a2[14] += xv * q3.z; a2[15] += xv * q3.w;
        }
        if (pj == 1) {
            #pragma unroll
            for (int j = 0; j < 16; j++) a2[j] = a2[j] / (1.f + __expf(-a2[j]));
        }
        float* dst = (pj == 0 ? g_x1 : g_zs) + (b * 1024 + p) * 128 + jb;
        *reinterpret_cast<float4*>(dst)      = make_float4(a2[0], a2[1], a2[2], a2[3]);
        *reinterpret_cast<float4*>(dst + 4)  = make_float4(a2[4], a2[5], a2[6], a2[7]);
        *reinterpret_cast<float4*>(dst + 8)  = make_float4(a2[8], a2[9], a2[10], a2[11]);
        *reinterpret_cast<float4*>(dst + 12) = make_float4(a2[12], a2[13], a2[14], a2[15]);
        __syncthreads();
    }
}

// ---------------- K2: depthwise 3x3 conv + bias + silu (NHWC, R7) ----------------
__global__ __launch_bounds__(128) void k2_conv(const float* __restrict__ cw,
                                               const float* __restrict__ cb) {
    int b = blockIdx.x >> 10, p = blockIdx.x & 1023;
    int h = p >> 5, w = p & 31, d = threadIdx.x;
    float s = cb[d];
    #pragma unroll
    for (int i = -1; i <= 1; i++) {
        int hh = h + i; if ((unsigned)hh >= 32u) continue;
        #pragma unroll
        for (int j = -1; j <= 1; j++) {
            int ww = w + j; if ((unsigned)ww >= 32u) continue;
            s += g_x1[(b * 1024 + hh * 32 + ww) * 128 + d] *
                 __ldg(&cw[d * 9 + (i + 1) * 3 + (j + 1)]);
        }
    }
    s = s / (1.f + __expf(-s));
    g_x1s[(b * 1024 + p) * 128 + d] = s;
}

// ---------------- K3: x_dbl = xs @ x_proj_w^T (R7) + clear carry flags ----------------
__global__ __launch_bounds__(128) void k3_xdbl(const float* __restrict__ xpw) {
    __shared__ float s_u[64 * 132];   // 33792 B
    int blk = blockIdx.x; int bk = blk >> 4, lt = blk & 15;
    int b = bk >> 2, k = bk & 3; int l0 = lt * 64;
    int t = threadIdx.x;
    if (t == 0 && blk < 256) g_flag[blk] = 0;  // clear carry flags (prev k4 long done)
    #pragma unroll 4
    for (int l = 0; l < 64; l++)
        s_u[l * 132 + t] = g_x1s[(b * 1024 + perm_idx(k, l0 + l)) * 128 + t];
    __syncthreads();
    int lsub = t & 31, cg = t >> 5;
    float acc0[9], acc1[9];
    #pragma unroll
    for (int j = 0; j < 9; j++) { acc0[j] = 0.f; acc1[j] = 0.f; }
    const float4* urow0 = reinterpret_cast<const float4*>(&s_u[lsub * 132]);
    const float4* urow1 = reinterpret_cast<const float4*>(&s_u[(lsub + 32) * 132]);
    const float4* wbase = reinterpret_cast<const float4*>(xpw + (k * 36 + cg * 9) * 128);
    #pragma unroll 4
    for (int d4 = 0; d4 < 32; d4++) {
        float4 u0 = urow0[d4];
        float4 u1 = urow1[d4];
        #pragma unroll
        for (int j = 0; j < 9; j++) {
            float4 wv = __ldg(&wbase[j * 32 + d4]);
            acc0[j] += u0.x * wv.x + u0.y * wv.y + u0.z * wv.z + u0.w * wv.w;
            acc1[j] += u1.x * wv.x + u1.y * wv.y + u1.z * wv.z + u1.w * wv.w;
        }
    }
    float* dst = g_xdbl + bk * 36 * 1024 + l0;
    #pragma unroll
    for (int j = 0; j < 9; j++) {
        dst[(cg * 9 + j) * 1024 + lsub]      = acc0[j];
        dst[(cg * 9 + j) * 1024 + lsub + 32] = acc1[j];
    }
}

// ================= K4 fused: 2-states/lane, 4-channels/warp layout =================
// block = 128 thr = 16 channels (d0..d0+15). Lane owns states (n, n+8), n=lane&7,
// channel ch = (warp<<2)|(lane>>3).
// Grid 768: [0,256) role A (carry l<512), [256,512) B0 (chunk0 emit),
// [512,768) B1 (chunk1 emit, spins on g_flag).
__global__ __launch_bounds__(128) void k4_fused(
    const float* __restrict__ alogs,
    const float* __restrict__ dtw, const float* __restrict__ dtb)
{
    __shared__ float2 s_b2[64 * 9];     // B pairs: [l][(n,n+8)]
    __shared__ float2 s_c2[64 * 9];     // C pairs
    __shared__ float  s_dts[4 * 68];
    __shared__ float2 s_dd[16 * 67];    // per-channel (delta, delta*u); 67 pad for STS.64
    __shared__ float  s_y[16 * 66];

    int blk = blockIdx.x;
    int role = blk >> 8;                 // 0=A, 1=B0, 2=B1
    int idx = blk & 255;                 // (bk, dg)
    int bk = idx >> 3, dg = idx & 7;
    int b = bk >> 2, k = bk & 3;
    int d0 = dg * 16;
    int t = threadIdx.x, warp = t >> 5, lane = t & 31;
    int ch = (warp << 2) | (lane >> 3);  // 0..15
    int n = lane & 7;
    int d = d0 + ch;

    float An0 = -expf(alogs[(k * 128 + d) * 16 + n]);
    float An1 = -expf(alogs[(k * 128 + d) * 16 + n + 8]);

    // dd-compute assignment: thread covers channel dl, l = lq + 8*i
    int dl = t & 15, lq = t >> 4;
    float4 w4 = *reinterpret_cast<const float4*>(&dtw[(k * 128 + d0 + dl) * 4]);
    float tb = dtb[k * 128 + d0 + dl];
    const float* xd = g_xdbl + bk * 36 * 1024;

    int c1 = (role == 2) ? 1 : 0;        // chunk for emit roles
    float h0 = 0.f, h1 = 0.f;
    if (role == 2) {
        if (t == 0) {
            while (atomicAdd(&g_flag[idx], 0) == 0) { }
        }
        __syncthreads();
        __threadfence();
        h0 = g_q[(bk * 128 + d) * 16 + n];
        h1 = g_q[(bk * 128 + d) * 16 + n + 8];
    }

    for (int sc = 0; sc < 8; sc++) {
        int gl0 = (role == 0) ? sc * 64 : (c1 * 512 + sc * 64);
        // stage B pairs (and C pairs for emit roles)
        #pragma unroll
        for (int i = 0; i < 4; i++) {
            int ii = i * 128 + t; int nn = ii >> 6, l = ii & 63;
            s_b2[l * 9 + nn] = make_float2(xd[(4 + nn) * 1024 + gl0 + l],
                                           xd[(12 + nn) * 1024 + gl0 + l]);
        }
        if (role != 0) {
            #pragma unroll
            for (int i = 0; i < 4; i++) {
                int ii = i * 128 + t; int nn = ii >> 6, l = ii & 63;
                s_c2[l * 9 + nn] = make_float2(xd[(20 + nn) * 1024 + gl0 + l],
                                               xd[(28 + nn) * 1024 + gl0 + l]);
            }
        }
        // stage dts rows 0..3
        #pragma unroll
        for (int i = 0; i < 2; i++) {
            int ii = i * 128 + t; int r = ii >> 6, l = ii & 63;
            s_dts[r * 68 + l] = xd[r * 1024 + gl0 + l];
        }
        __syncthreads();
        // delta & delta*u for 16 channels x 64 l
        #pragma unroll
        for (int i = 0; i < 8; i++) {
            int l = lq + i * 8;
            float x = tb + s_dts[l] * w4.x + s_dts[68 + l] * w4.y
                         + s_dts[136 + l] * w4.z + s_dts[204 + l] * w4.w;
            float e = __expf(x);
            float delta = (x > 20.f) ? x : __logf(1.f + e);
            float u = g_x1s[(b * 1024 + perm_idx(k, gl0 + l)) * 128 + d0 + dl];
            s_dd[dl * 67 + l] = make_float2(delta, delta * u);
        }
        __syncthreads();

        if (role == 0) {
            #pragma unroll 4
            for (int l = 0; l < 64; l++) {
                float2 dd = s_dd[ch * 67 + l];
                float e0 = __expf(dd.x * An0);
                float e1 = __expf(dd.x * An1);
                float2 B = s_b2[l * 9 + n];
                h0 = h0 * e0 + dd.y * B.x;
                h1 = h1 * e1 + dd.y * B.y;
            }
        } else {
            #pragma unroll 4
            for (int l = 0; l < 64; l++) {
                float2 dd = s_dd[ch * 67 + l];
                float e0 = __expf(dd.x * An0);
                float e1 = __expf(dd.x * An1);
                float2 B = s_b2[l * 9 + n];
                h0 = h0 * e0 + dd.y * B.x;
                h1 = h1 * e1 + dd.y * B.y;
                float2 C = s_c2[l * 9 + n];
                float yv = h0 * C.x + h1 * C.y;
                yv += __shfl_xor_sync(0xffffffffu, yv, 4);
                yv += __shfl_xor_sync(0xffffffffu, yv, 2);
                yv += __shfl_xor_sync(0xffffffffu, yv, 1);
                if (n == 0) s_y[ch * 66 + l] = yv;
            }
        }
        __syncthreads();
        if (role != 0) {
            // writeback: 16 ch x 64 l, coalesced over dl
            #pragma unroll
            for (int i = 0; i < 8; i++) {
                int l = i * 8 + lq;
                g_ys[(bk * 1024 + gl0 + l) * 128 + d0 + dl] = s_y[dl * 66 + l];
            }
        }
        __syncthreads();
    }

    if (role == 0) {
        g_q[(bk * 128 + d) * 16 + n]     = h0;
        g_q[(bk * 128 + d) * 16 + n + 8] = h1;
        __syncthreads();
        if (t == 0) {
            __threadfence();
            atomicExch(&g_flag[idx], 1);
        }
    }
}

// ---------------- K5: combine 4 dirs + D*x + LN + gate + out_proj + residual + LN + z_mamba (R7) ----------------
__global__ __launch_bounds__(128) void k5_back(
    const float* __restrict__ Ds, const float* __restrict__ ong,
    const float* __restrict__ onb, const float* __restrict__ opw,
    const float* __restrict__ mg, const float* __restrict__ mb)
{
    __shared__ float s_y[128];
    __shared__ float s_red[8];
    __shared__ float s_st[4];
    int b = blockIdx.x >> 10, p = blockIdx.x & 1023;
    int tp = (p & 31) * 32 + (p >> 5);
    int t = threadIdx.x, d = t;
    int b4 = b * 4;
    float y = g_ys[((b4 + 0) * 1024 + p) * 128 + d]
            + g_ys[((b4 + 2) * 1024 + (1023 - p)) * 128 + d]
            + g_ys[((b4 + 1) * 1024 + tp) * 128 + d]
            + g_ys[((b4 + 3) * 1024 + (1023 - tp)) * 128 + d];
    float sds = Ds[d] + Ds[128 + d] + Ds[256 + d] + Ds[384 + d];
    y += sds * g_x1s[(b * 1024 + p) * 128 + d];

    float s1 = y, s2 = y * y;
    #pragma unroll
    for (int o = 16; o; o >>= 1) {
        s1 += __shfl_xor_sync(0xffffffffu, s1, o);
        s2 += __shfl_xor_sync(0xffffffffu, s2, o);
    }
    if ((t & 31) == 0) { s_red[t >> 5] = s1; s_red[4 + (t >> 5)] = s2; }
    __syncthreads();
    if (t == 0) {
        float a = s_red[0] + s_red[1] + s_red[2] + s_red[3];
        float q = s_red[4] + s_red[5] + s_red[6] + s_red[7];
        float mu = a * (1.f / 128.f);
        float var = q * (1.f / 128.f) - mu * mu;
        s_st[0] = mu; s_st[1] = rsqrtf(var + EPS);
    }
    __syncthreads();
    float yn = (y - s_st[0]) * s_st[1] * ong[d] + onb[d];
    yn *= g_zs[(b * 1024 + p) * 128 + d];
    s_y[d] = yn;
    __syncthreads();

    float xm = 0.f;
    if (t < 64) {
        float acc = 0.f;
        const float4* w4 = reinterpret_cast<const float4*>(opw + t * 128);
        const float4* y4 = reinterpret_cast<const float4*>(s_y);
        #pragma unroll 8
        for (int i = 0; i < 32; i++) {
            float4 a = y4[i], ww = __ldg(&w4[i]);
            acc += a.x * ww.x + a.y * ww.y + a.z * ww.z + a.w * ww.w;
        }
        xm = g_x[(b * 1024 + p) * 64 + t] + acc;
    }
    float s1b = (t < 64) ? xm : 0.f, s2b = (t < 64) ? xm * xm : 0.f;
    #pragma unroll
    for (int o = 16; o; o >>= 1) {
        s1b += __shfl_xor_sync(0xffffffffu, s1b, o);
        s2b += __shfl_xor_sync(0xffffffffu, s2b, o);
    }
    if ((t & 31) == 0) { s_red[t >> 5] = s1b; s_red[4 + (t >> 5)] = s2b; }
    __syncthreads();
    if (t == 0) {
        float a = s_red[0] + s_red[1];
        float q = s_red[4] + s_red[5];
        float mu = a * (1.f / 64.f);
        float var = q * (1.f / 64.f) - mu * mu;
        s_st[2] = mu; s_st[3] = rsqrtf(var + EPS);
    }
    __syncthreads();
    if (t < 64) {
        float v = (xm - s_st[2]) * s_st[3] * mg[t] + mb[t];
        atomicAdd(&g_zj[b * 576 + 512 + t], v * (1.f / 1024.f));
    }
}

// ---------------- K6: joint-embed MLP head (warp-coalesced, R7) ----------------
__global__ __launch_bounds__(256) void k6_head(
    const float* __restrict__ w1, const float* __restrict__ g1,
    const float* __restrict__ b1, const float* __restrict__ m1,
    const float* __restrict__ v1, const float* __restrict__ w2)
{
    __shared__ float s_z[576];
    __shared__ float s_h[64];
    int b = blockIdx.x, t = threadIdx.x;
    int warp = t >> 5, lane = t & 31;
    for (int i = t; i < 576; i += 256) s_z[i] = g_zj[b * 576 + i];
    __syncthreads();

    #pragma unroll
    for (int mi = 0; mi < 8; mi++) {
        int m = warp * 8 + mi;
        float acc = 0.f;
        #pragma unroll 6
        for (int jk = 0; jk < 18; jk++) {
            int j = lane + jk * 32;
            acc += s_z[j] * __ldg(&w1[m * 576 + j]);
        }
        #pragma unroll
        for (int o = 16; o; o >>= 1) acc += __shfl_xor_sync(0xffffffffu, acc, o);
        if (lane == 0) {
            float hm = (acc - m1[m]) * rsqrtf(v1[m] + EPS) * g1[m] + b1[m];
            s_h[m] = fmaxf(hm, 0.f);
        }
    }
    __syncthreads();

    float zl0 = s_h[lane], zl1 = s_h[lane + 32];
    for (int oi = 0; oi < 64; oi++) {
        int o = warp * 64 + oi;
        float acc = zl0 * __ldg(&w2[o * 64 + lane]) + zl1 * __ldg(&w2[o * 64 + lane + 32]);
        #pragma unroll
        for (int q = 16; q; q >>= 1) acc += __shfl_xor_sync(0xffffffffu, acc, q);
        if (lane == 0) g_wgt[b * 512 + o] = 1.f / (1.f + __expf(-acc));
    }
}

// ---------------- K7: out = rgb*(1+wr) + dem*(1+wd) ----------------
__global__ __launch_bounds__(256) void k7_out(const float* __restrict__ rgb,
                                              const float* __restrict__ dem,
                                              float* __restrict__ out) {
    int idx = blockIdx.x * 256 + threadIdx.x;
    int b = idx >> 18;
    int c = (idx >> 10) & 255;
    float wr = g_wgt[b * 512 + c];
    float wd = g_wgt[b * 512 + 256 + c];
    out[idx] = rgb[idx] * (1.f + wr) + dem[idx] * (1.f + wd);
}

// ---------------- launch ----------------
extern "C" void kernel_launch(void* const* d_in, const int* in_sizes, int n_in,
                              void* d_out, int out_size) {
    const float* rgb   = (const float*)d_in[0];
    const float* dem   = (const float*)d_in[1];
    const float* wred  = (const float*)d_in[2];
    const float* bnr_g = (const float*)d_in[3];
    const float* bnr_b = (const float*)d_in[4];
    const float* bnr_m = (const float*)d_in[5];
    const float* bnr_v = (const float*)d_in[6];
    const float* ln1_g = (const float*)d_in[7];
    const float* ln1_b = (const float*)d_in[8];
    const float* ipw   = (const float*)d_in[9];
    const float* convw = (const float*)d_in[10];
    const float* convb = (const float*)d_in[11];
    const float* xpw   = (const float*)d_in[12];
    const float* dtw   = (const float*)d_in[13];
    const float* dtb   = (const float*)d_in[14];
    const float* alogs = (const float*)d_in[15];
    const float* Ds    = (const float*)d_in[16];
    const float* on_g  = (const float*)d_in[17];
    const float* on_b  = (const float*)d_in[18];
    const float* opw   = (const float*)d_in[19];
    const float* mno_g = (const float*)d_in[20];
    const float* mno_b = (const float*)d_in[21];
    const float* je_w1 = (const float*)d_in[22];
    const float* bn1_g = (const float*)d_in[23];
    const float* bn1_b = (const float*)d_in[24];
    const float* bn1_m = (const float*)d_in[25];
    const float* bn1_v = (const float*)d_in[26];
    const float* je_w2 = (const float*)d_in[27];
    float* out = (float*)d_out;

    k0_means<<<512, 256>>>(rgb, dem);
    k1_front<<<256, 256>>>(rgb, dem, wred, bnr_g, bnr_b, bnr_m, bnr_v,
                           ln1_g, ln1_b, ipw);
    k2_conv<<<8192, 128>>>(convw, convb);
    k3_xdbl<<<512, 128>>>(xpw);
    k4_fused<<<768, 128>>>(alogs, dtw, dtb);
    k5_back<<<8192, 128>>>(Ds, on_g, on_b, opw, mno_g, mno_b);
    k6_head<<<8, 256>>>(je_w1, bn1_g, bn1_b, bn1_m, bn1_v, je_w2);
    k7_out<<<8192, 256>>>(rgb, dem, out);
}